// round 15
// baseline (speedup 1.0000x reference)
#include <cuda_runtime.h>

// Shapes: L=4, B=8, C=256, H=W=64
#define LN 4
#define BN 8
#define CN 256
#define HW 4096
#define GRIDN (LN*CN)            // 1024 blocks: one slab (l, c) per batch
#define TPB 256
#define LAG 1                    // finish batch b-1 while reading batch b
#define READY_TARGET GRIDN       // 1 gap publish per block per batch

__device__ float g_gap[LN*BN*CN];
__device__ int   g_ready[BN];

// Zero flags each call (graph-replay safe).
__global__ void init_kernel() {
    if (threadIdx.x < BN) g_ready[threadIdx.x] = 0;
}

__device__ __forceinline__ int poll_cg(const int* p) {
    int r;
    asm volatile("ld.global.cg.s32 %0, [%1];" : "=r"(r) : "l"(p));
    return r;
}

// Block (l = bid>>8, c = bid&255) owns slab (l, b, c) for every batch b.
// Iteration b: [A] stream-read batch-b slab (lines land in L1+L2), reduce,
//                  publish gap + ticket;
//              [B] finish batch b-1: poll ticket (A(b) issued first, so the
//                  flag is normally already set), scores + softmax, re-read
//                  slab from L1 (128 KB window < 228 KB L1), scale, store.
// <=32 regs -> 8 blocks/SM -> 64 warps/SM; 1184 resident >= 1024: flag waits
// are deadlock-free.
__global__ __launch_bounds__(TPB, 8) void main_kernel(const float* __restrict__ in,
                                                      const float* __restrict__ Wlin,
                                                      float* __restrict__ out) {
    const int bid = blockIdx.x;
    const int c   = bid & 255;
    const int l   = bid >> 8;
    const int tid = threadIdx.x;

    __shared__ float s_warp[8];
    __shared__ float s_sc[LN];

    for (int b = 0; b < BN + LAG; ++b) {
        // ---- [A] read + reduce batch-b slab, publish ----
        if (b < BN) {
            const float4* p = reinterpret_cast<const float4*>(in)
                            + (size_t)((l * BN + b) * CN + c) * 1024;
            float acc = 0.0f;
#pragma unroll
            for (int k = 0; k < 4; ++k) {
                float4 v = __ldg(p + tid + k * 256);   // allocate L1+L2
                acc += (v.x + v.y) + (v.z + v.w);
            }
#pragma unroll
            for (int off = 16; off; off >>= 1)
                acc += __shfl_down_sync(0xffffffffu, acc, off);
            if ((tid & 31) == 0) s_warp[tid >> 5] = acc;
            __syncthreads();
            if (tid == 0) {
                float t = 0.0f;
#pragma unroll
                for (int w = 0; w < 8; ++w) t += s_warp[w];
                __stcg(&g_gap[(l * BN + b) * CN + c], t * (1.0f / (float)HW));
                __threadfence();                       // release gap before ticket
                atomicAdd(&g_ready[b], 1);
            }
        }

        // ---- [B] finish batch b-LAG ----
        if (b >= LAG) {
            const int bb = b - LAG;
            if (tid == 0)
                while (poll_cg(&g_ready[bb]) < READY_TARGET) __nanosleep(64);
            __syncthreads();

            // Scores: warp w -> level w; lane j covers c' = j*8..j*8+7.
            const int w = tid >> 5, j = tid & 31;
            if (w < LN) {
                const float4* gp = reinterpret_cast<const float4*>(g_gap + (w * BN + bb) * CN) + j * 2;
                const float4* wp = reinterpret_cast<const float4*>(Wlin + (size_t)c * CN) + j * 2;
                float4 g0 = __ldcg(gp), g1 = __ldcg(gp + 1);   // L2-coherent gap read
                float4 w0 = __ldg(wp), w1 = __ldg(wp + 1);
                float sc = g0.x * w0.x + g0.y * w0.y + g0.z * w0.z + g0.w * w0.w
                         + g1.x * w1.x + g1.y * w1.y + g1.z * w1.z + g1.w * w1.w;
#pragma unroll
                for (int off = 16; off; off >>= 1)
                    sc += __shfl_down_sync(0xffffffffu, sc, off);
                if (j == 0) s_sc[w] = sc;
            }
            __syncthreads();

            float m  = fmaxf(fmaxf(s_sc[0], s_sc[1]), fmaxf(s_sc[2], s_sc[3]));
            float e0 = __expf(s_sc[0] - m), e1 = __expf(s_sc[1] - m);
            float e2 = __expf(s_sc[2] - m), e3 = __expf(s_sc[3] - m);
            float inv = 1.0f / ((e0 + e1) + (e2 + e3));
            const float a = (l == 0 ? e0 : l == 1 ? e1 : l == 2 ? e2 : e3) * inv;

            // Re-read batch-bb slab: this block loaded it last iteration ->
            // still L1-resident (128 KB window). Plain cached load.
            const size_t slab = (size_t)((l * BN + bb) * CN + c);
            const float4* pi = reinterpret_cast<const float4*>(in)  + slab * 1024;
            float4*       po = reinterpret_cast<float4*>(out)       + slab * 1024;
#pragma unroll
            for (int k = 0; k < 4; ++k) {
                float4 v = pi[tid + k * 256];            // L1 hit expected
                v.x *= a; v.y *= a; v.z *= a; v.w *= a;
                __stcs(po + tid + k * 256, v);           // evict-first
            }
        }
        __syncthreads();   // protect s_warp / s_sc across iterations
    }
}

extern "C" void kernel_launch(void* const* d_in, const int* in_sizes, int n_in,
                              void* d_out, int out_size) {
    const float* in   = (const float*)d_in[0];   // [4,8,256,64,64]
    const float* Wlin = (const float*)d_in[1];   // [256,256]
    float* out = (float*)d_out;

    init_kernel<<<1, 32>>>();
    main_kernel<<<GRIDN, TPB>>>(in, Wlin, out);
}